// round 3
// baseline (speedup 1.0000x reference)
#include <cuda_runtime.h>

#define BATCH 2
#define SEQ   2048
#define HID   1024
#define NH    16
#define HD    64
#define QKV_O 1152            // NH*HD + 2*HD
#define ROWS  (BATCH * SEQ)   // 4096

#define ATTN_PAD 68
#define ATTN_SMEM_FLOATS (4 * 64 * ATTN_PAD + 3 * 64)
#define ATTN_SMEM_BYTES  (ATTN_SMEM_FLOATS * 4)

// Scratch (allocation-free): raw/normalized QKV and attention output.
__device__ float g_qkv[(size_t)ROWS * QKV_O];
__device__ float g_attn[(size_t)ROWS * HID];

// ---------------------------------------------------------------------------
// GEMM (NT): C[M,N] = A[M,K] * B[N,K]^T.  M,N multiples of 128, K multiple of 8.
// 128x128 tile, BK=8, 256 threads, 8x8 per-thread register blocking.
// ---------------------------------------------------------------------------
__global__ void __launch_bounds__(256, 2)
gemm_nt_kernel(const float* __restrict__ A, const float* __restrict__ Bm,
               float* __restrict__ C, int M, int N, int K)
{
    __shared__ float As[8][132];
    __shared__ float Bs[8][132];

    const int tid = threadIdx.x;
    const int bm = blockIdx.y, bn = blockIdx.x;

    const float* Ab = A + (size_t)bm * 128 * K;
    const float* Bb = Bm + (size_t)bn * 128 * K;
    float* Cb = C + (size_t)bm * 128 * N + (size_t)bn * 128;

    const int lrow = tid >> 1;         // 0..127
    const int lq   = (tid & 1) * 4;    // 0 or 4
    const int tm = tid >> 4;           // 0..15
    const int tn = tid & 15;           // 0..15

    float acc[8][8];
#pragma unroll
    for (int i = 0; i < 8; i++)
#pragma unroll
        for (int j = 0; j < 8; j++) acc[i][j] = 0.f;

    for (int k0 = 0; k0 < K; k0 += 8) {
        float4 av = *reinterpret_cast<const float4*>(Ab + (size_t)lrow * K + k0 + lq);
        float4 bv = *reinterpret_cast<const float4*>(Bb + (size_t)lrow * K + k0 + lq);
        __syncthreads();
        As[lq + 0][lrow] = av.x; As[lq + 1][lrow] = av.y;
        As[lq + 2][lrow] = av.z; As[lq + 3][lrow] = av.w;
        Bs[lq + 0][lrow] = bv.x; Bs[lq + 1][lrow] = bv.y;
        Bs[lq + 2][lrow] = bv.z; Bs[lq + 3][lrow] = bv.w;
        __syncthreads();
#pragma unroll
        for (int kk = 0; kk < 8; kk++) {
            float4 a0 = *reinterpret_cast<const float4*>(&As[kk][tm * 4]);
            float4 a1 = *reinterpret_cast<const float4*>(&As[kk][64 + tm * 4]);
            float4 b0 = *reinterpret_cast<const float4*>(&Bs[kk][tn * 4]);
            float4 b1 = *reinterpret_cast<const float4*>(&Bs[kk][64 + tn * 4]);
            float ar[8] = {a0.x, a0.y, a0.z, a0.w, a1.x, a1.y, a1.z, a1.w};
            float br[8] = {b0.x, b0.y, b0.z, b0.w, b1.x, b1.y, b1.z, b1.w};
#pragma unroll
            for (int i = 0; i < 8; i++)
#pragma unroll
                for (int j = 0; j < 8; j++)
                    acc[i][j] += ar[i] * br[j];
        }
    }

#pragma unroll
    for (int rg = 0; rg < 2; rg++)
#pragma unroll
        for (int r = 0; r < 4; r++) {
            int row = rg * 64 + tm * 4 + r;
#pragma unroll
            for (int cg = 0; cg < 2; cg++) {
                float4 v;
                v.x = acc[rg * 4 + r][cg * 4 + 0];
                v.y = acc[rg * 4 + r][cg * 4 + 1];
                v.z = acc[rg * 4 + r][cg * 4 + 2];
                v.w = acc[rg * 4 + r][cg * 4 + 3];
                *reinterpret_cast<float4*>(Cb + (size_t)row * N + cg * 64 + tn * 4) = v;
            }
        }
}

// ---------------------------------------------------------------------------
// LayerNorm over the 1152-wide QKV rows, in place in g_qkv.
// ---------------------------------------------------------------------------
__global__ void __launch_bounds__(256)
ln_kernel(const float* __restrict__ gamma, const float* __restrict__ beta)
{
    const int row = blockIdx.x;
    float* p = g_qkv + (size_t)row * QKV_O;
    const int tid = threadIdx.x;

    float s = 0.f, sq = 0.f;
    for (int i = tid; i < QKV_O; i += 256) {
        float v = p[i];
        s += v;
        sq += v * v;
    }
    __shared__ float red[256], red2[256];
    red[tid] = s; red2[tid] = sq;
    __syncthreads();
    for (int off = 128; off > 0; off >>= 1) {
        if (tid < off) {
            red[tid] += red[tid + off];
            red2[tid] += red2[tid + off];
        }
        __syncthreads();
    }
    const float inv_n = 1.0f / (float)QKV_O;
    float mean = red[0] * inv_n;
    float var = red2[0] * inv_n - mean * mean;
    float rstd = rsqrtf(var + 1e-5f);

    for (int i = tid; i < QKV_O; i += 256) {
        p[i] = (p[i] - mean) * rstd * gamma[i] + beta[i];
    }
}

// ---------------------------------------------------------------------------
// Causal MQA flash attention. One block per (q_tile of 64, head, batch).
// Row layout of g_qkv: [0..63]=K, [64..127]=V, [128 + h*64 ..]=Q head h.
// Online softmax; two 64x64x64 fp32 mini-GEMMs per KV tile.
//   Qs [d][i], Ks [d][j], Vs [j][d], Ps [j][i]   (pad = 68 floats per row)
// ---------------------------------------------------------------------------
__global__ void __launch_bounds__(256)
attn_kernel()
{
    extern __shared__ float sm[];
    float* Qs = sm;                      // [64][ATTN_PAD] as [d][i]
    float* Ks = Qs + 64 * ATTN_PAD;      // [d][j]
    float* Vs = Ks + 64 * ATTN_PAD;      // [j][d]
    float* Ps = Vs + 64 * ATTN_PAD;      // [j][i]
    float* rowm = Ps + 64 * ATTN_PAD;    // [64]
    float* rowl = rowm + 64;
    float* rowscale = rowl + 64;

    const int tid = threadIdx.x;
    const int b = blockIdx.z, h = blockIdx.y;
    const int qt = 31 - blockIdx.x;      // heavy (long) tiles scheduled first
    const int q0 = qt * 64;
    const float* base = g_qkv + (size_t)b * SEQ * QKV_O;
    const int qoff = 2 * HD + h * HD;
    const float scale = 0.125f;          // 1/sqrt(64)

    // Load Q tile transposed: Qs[d][i] = Q[q0+i][d]
#pragma unroll
    for (int it = 0; it < 4; it++) {
        int f4 = tid + it * 256;         // 0..1023
        int i = f4 >> 4;
        int d4 = (f4 & 15) * 4;
        float4 v = *reinterpret_cast<const float4*>(base + (size_t)(q0 + i) * QKV_O + qoff + d4);
        Qs[(d4 + 0) * ATTN_PAD + i] = v.x;
        Qs[(d4 + 1) * ATTN_PAD + i] = v.y;
        Qs[(d4 + 2) * ATTN_PAD + i] = v.z;
        Qs[(d4 + 3) * ATTN_PAD + i] = v.w;
    }
    if (tid < 64) {
        rowm[tid] = -3.0e38f;
        rowl[tid] = 0.f;
    }

    const int tm = tid >> 4, tn = tid & 15;
    float acc[4][4];                     // O[i = tm*4+r][d = tn*4+c]
#pragma unroll
    for (int r = 0; r < 4; r++)
#pragma unroll
        for (int c = 0; c < 4; c++) acc[r][c] = 0.f;

    __syncthreads();

    for (int kt = 0; kt <= qt; kt++) {
        const int k0 = kt * 64;

        // Load K (transposed) and V tiles
#pragma unroll
        for (int it = 0; it < 4; it++) {
            int f4 = tid + it * 256;
            int j = f4 >> 4;
            int d4 = (f4 & 15) * 4;
            const float* src = base + (size_t)(k0 + j) * QKV_O;
            float4 kv = *reinterpret_cast<const float4*>(src + d4);       // K at offset 0
            float4 vv = *reinterpret_cast<const float4*>(src + HD + d4);  // V at offset 64
            Ks[(d4 + 0) * ATTN_PAD + j] = kv.x;
            Ks[(d4 + 1) * ATTN_PAD + j] = kv.y;
            Ks[(d4 + 2) * ATTN_PAD + j] = kv.z;
            Ks[(d4 + 3) * ATTN_PAD + j] = kv.w;
            *reinterpret_cast<float4*>(&Vs[j * ATTN_PAD + d4]) = vv;
        }
        __syncthreads();

        // S^T mini-GEMM: thread computes S[j = tm*4+r][i = tn*4+c]
        float s[4][4];
#pragma unroll
        for (int r = 0; r < 4; r++)
#pragma unroll
            for (int c = 0; c < 4; c++) s[r][c] = 0.f;
#pragma unroll
        for (int d = 0; d < 64; d++) {
            float4 kf = *reinterpret_cast<const float4*>(&Ks[d * ATTN_PAD + tm * 4]);
            float4 qf = *reinterpret_cast<const float4*>(&Qs[d * ATTN_PAD + tn * 4]);
            float kr[4] = {kf.x, kf.y, kf.z, kf.w};
            float qr[4] = {qf.x, qf.y, qf.z, qf.w};
#pragma unroll
            for (int r = 0; r < 4; r++)
#pragma unroll
                for (int c = 0; c < 4; c++)
                    s[r][c] += kr[r] * qr[c];
        }

        // Scale + causal mask, store Ps[j][i]
        const bool diag = (kt == qt);
#pragma unroll
        for (int r = 0; r < 4; r++) {
            int j = tm * 4 + r;
            float4 v;
            float* vp = &v.x;
#pragma unroll
            for (int c = 0; c < 4; c++) {
                int i = tn * 4 + c;
                float val = s[r][c] * scale;
                if (diag && (j > i)) val = -1e30f;
                vp[c] = val;
            }
            *reinterpret_cast<float4*>(&Ps[j * ATTN_PAD + tn * 4]) = v;
        }
        __syncthreads();

        // Online softmax: thread i (< 64) owns query row i
        if (tid < 64) {
            const int i = tid;
            float m_old = rowm[i];
            float mx = m_old;
#pragma unroll 8
            for (int j = 0; j < 64; j++)
                mx = fmaxf(mx, Ps[j * ATTN_PAD + i]);
            float sum = 0.f;
#pragma unroll 8
            for (int j = 0; j < 64; j++) {
                float pv = __expf(Ps[j * ATTN_PAD + i] - mx);
                Ps[j * ATTN_PAD + i] = pv;
                sum += pv;
            }
            float corr = __expf(m_old - mx);
            rowl[i] = rowl[i] * corr + sum;
            rowm[i] = mx;
            rowscale[i] = corr;
        }
        __syncthreads();

        // O rescale + P@V accumulate
#pragma unroll
        for (int r = 0; r < 4; r++) {
            float cf = rowscale[tm * 4 + r];
#pragma unroll
            for (int c = 0; c < 4; c++) acc[r][c] *= cf;
        }
#pragma unroll
        for (int j = 0; j < 64; j++) {
            float4 pf = *reinterpret_cast<const float4*>(&Ps[j * ATTN_PAD + tm * 4]);
            float4 vf = *reinterpret_cast<const float4*>(&Vs[j * ATTN_PAD + tn * 4]);
            float pr[4] = {pf.x, pf.y, pf.z, pf.w};
            float vr[4] = {vf.x, vf.y, vf.z, vf.w};
#pragma unroll
            for (int r = 0; r < 4; r++)
#pragma unroll
                for (int c = 0; c < 4; c++)
                    acc[r][c] += pr[r] * vr[c];
        }
        __syncthreads();
    }

    // Normalize and write O: g_attn[b*SEQ + q0 + i][h*64 + d]
#pragma unroll
    for (int r = 0; r < 4; r++) {
        int i = tm * 4 + r;
        float inv = 1.0f / rowl[i];
        float4 v;
        v.x = acc[r][0] * inv;
        v.y = acc[r][1] * inv;
        v.z = acc[r][2] * inv;
        v.w = acc[r][3] * inv;
        *reinterpret_cast<float4*>(
            &g_attn[(size_t)(b * SEQ + q0 + i) * HID + h * HD + tn * 4]) = v;
    }
}

// ---------------------------------------------------------------------------
extern "C" void kernel_launch(void* const* d_in, const int* in_sizes, int n_in,
                              void* d_out, int out_size)
{
    const float* x     = (const float*)d_in[0];   // (2, 2048, 1024)
    const float* Wqkv  = (const float*)d_in[1];   // (1152, 1024)
    const float* gamma = (const float*)d_in[2];   // (1152,)
    const float* beta  = (const float*)d_in[3];   // (1152,)
    const float* Wfc   = (const float*)d_in[4];   // (1024, 1024)
    float* out = (float*)d_out;                   // (2, 2048, 1024)

    void* qkv_p = nullptr;
    void* attn_p = nullptr;
    cudaGetSymbolAddress(&qkv_p, g_qkv);
    cudaGetSymbolAddress(&attn_p, g_attn);
    float* qkv = (float*)qkv_p;
    float* attn = (float*)attn_p;

    cudaFuncSetAttribute(attn_kernel,
                         cudaFuncAttributeMaxDynamicSharedMemorySize,
                         ATTN_SMEM_BYTES);

    dim3 blk(256);

    // 1) QKV GEMM: g_qkv[4096, 1152] = x[4096, 1024] @ Wqkv[1152, 1024]^T
    gemm_nt_kernel<<<dim3(QKV_O / 128, ROWS / 128), blk>>>(x, Wqkv, qkv, ROWS, QKV_O, HID);

    // 2) LayerNorm in place
    ln_kernel<<<ROWS, blk>>>(gamma, beta);

    // 3) Causal MQA attention -> g_attn[4096, 1024]
    attn_kernel<<<dim3(SEQ / 64, NH, BATCH), blk, ATTN_SMEM_BYTES>>>();

    // 4) Output projection: out[4096, 1024] = g_attn @ Wfc[1024, 1024]^T
    gemm_nt_kernel<<<dim3(HID / 128, ROWS / 128), blk>>>(attn, Wfc, out, ROWS, HID, HID);
}

// round 4
// speedup vs baseline: 2.6937x; 2.6937x over previous
#include <cuda_runtime.h>
#include <cstdint>

#define BATCH 2
#define SEQ   2048
#define HID   1024
#define NH    16
#define HD    64
#define QKV_O 1152            // NH*HD + 2*HD
#define ROWS  (BATCH * SEQ)   // 4096

// Scratch (allocation-free)
__device__ float g_qkv[(size_t)ROWS * QKV_O];
__device__ float g_attn[(size_t)ROWS * HID];

// ---------------------------------------------------------------------------
// TF32 helpers
// ---------------------------------------------------------------------------
__device__ __forceinline__ unsigned f2t(float x) {
    unsigned u;
    asm("cvt.rna.tf32.f32 %0, %1;" : "=r"(u) : "f"(x));
    return u;
}

// D(16x8,f32) += A(16x8,tf32,row) * B(8x8,tf32,col)
__device__ __forceinline__ void mma8(float* d, const unsigned* a, const unsigned* b) {
    asm volatile(
        "mma.sync.aligned.m16n8k8.row.col.f32.tf32.tf32.f32 "
        "{%0,%1,%2,%3}, {%4,%5,%6,%7}, {%8,%9}, {%0,%1,%2,%3};\n"
        : "+f"(d[0]), "+f"(d[1]), "+f"(d[2]), "+f"(d[3])
        : "r"(a[0]), "r"(a[1]), "r"(a[2]), "r"(a[3]), "r"(b[0]), "r"(b[1]));
}

// ---------------------------------------------------------------------------
// GEMM (NT): C[M,N] = A[M,K] * B[N,K]^T, tf32 tensor cores, fp32 accumulate.
// Block 128x128, BK=16, 256 threads = 8 warps in 2(m) x 4(n); warp tile 64x32.
// Smem stride 20 (== 20 mod 32) -> conflict-free fragment LDS for the
// (row = lane/4, col = lane%4) access pattern.
// ---------------------------------------------------------------------------
__global__ void __launch_bounds__(256, 2)
gemm_nt_tc(const float* __restrict__ A, const float* __restrict__ Bm,
           float* __restrict__ C, int M, int N, int K)
{
    __shared__ unsigned As[128 * 20];
    __shared__ unsigned Bs[128 * 20];

    const int tid = threadIdx.x;
    const int lane = tid & 31, warp = tid >> 5;
    const int wm = warp >> 2, wn = warp & 3;
    const int r = lane >> 2, c = lane & 3;
    const int bm = blockIdx.y, bn = blockIdx.x;

    const float* Ab = A + (size_t)bm * 128 * K;
    const float* Bb = Bm + (size_t)bn * 128 * K;

    const int srow = tid >> 1;          // 0..127
    const int sk = (tid & 1) * 8;       // 0 or 8

    float acc[4][4][4];
#pragma unroll
    for (int i = 0; i < 4; i++)
#pragma unroll
        for (int j = 0; j < 4; j++)
#pragma unroll
            for (int k = 0; k < 4; k++) acc[i][j][k] = 0.f;

    // prefetch first k-slab into registers
    float4 a0v = *(const float4*)(Ab + (size_t)srow * K + sk);
    float4 a1v = *(const float4*)(Ab + (size_t)srow * K + sk + 4);
    float4 b0v = *(const float4*)(Bb + (size_t)srow * K + sk);
    float4 b1v = *(const float4*)(Bb + (size_t)srow * K + sk + 4);

    const int niter = K / 16;
    for (int it = 0; it < niter; it++) {
        unsigned* ap = &As[srow * 20 + sk];
        ap[0] = f2t(a0v.x); ap[1] = f2t(a0v.y); ap[2] = f2t(a0v.z); ap[3] = f2t(a0v.w);
        ap[4] = f2t(a1v.x); ap[5] = f2t(a1v.y); ap[6] = f2t(a1v.z); ap[7] = f2t(a1v.w);
        unsigned* bp = &Bs[srow * 20 + sk];
        bp[0] = f2t(b0v.x); bp[1] = f2t(b0v.y); bp[2] = f2t(b0v.z); bp[3] = f2t(b0v.w);
        bp[4] = f2t(b1v.x); bp[5] = f2t(b1v.y); bp[6] = f2t(b1v.z); bp[7] = f2t(b1v.w);
        __syncthreads();

        if (it + 1 < niter) {
            int ko = (it + 1) * 16 + sk;
            a0v = *(const float4*)(Ab + (size_t)srow * K + ko);
            a1v = *(const float4*)(Ab + (size_t)srow * K + ko + 4);
            b0v = *(const float4*)(Bb + (size_t)srow * K + ko);
            b1v = *(const float4*)(Bb + (size_t)srow * K + ko + 4);
        }

#pragma unroll
        for (int ks = 0; ks < 2; ks++) {
            unsigned af[4][4], bf[4][2];
#pragma unroll
            for (int mt = 0; mt < 4; mt++) {
                const unsigned* p = &As[(wm * 64 + mt * 16 + r) * 20 + ks * 8 + c];
                af[mt][0] = p[0];
                af[mt][1] = p[8 * 20];
                af[mt][2] = p[4];
                af[mt][3] = p[8 * 20 + 4];
            }
#pragma unroll
            for (int nt = 0; nt < 4; nt++) {
                const unsigned* p = &Bs[(wn * 32 + nt * 8 + r) * 20 + ks * 8 + c];
                bf[nt][0] = p[0];
                bf[nt][1] = p[4];
            }
#pragma unroll
            for (int mt = 0; mt < 4; mt++)
#pragma unroll
                for (int nt = 0; nt < 4; nt++)
                    mma8(acc[mt][nt], af[mt], bf[nt]);
        }
        __syncthreads();
    }

    float* Cb = C + (size_t)bm * 128 * N + (size_t)bn * 128;
#pragma unroll
    for (int mt = 0; mt < 4; mt++)
#pragma unroll
        for (int nt = 0; nt < 4; nt++) {
            int row = wm * 64 + mt * 16 + r;
            int col = wn * 32 + nt * 8 + 2 * c;
            *(float2*)(Cb + (size_t)row * N + col) =
                make_float2(acc[mt][nt][0], acc[mt][nt][1]);
            *(float2*)(Cb + (size_t)(row + 8) * N + col) =
                make_float2(acc[mt][nt][2], acc[mt][nt][3]);
        }
}

// ---------------------------------------------------------------------------
// LayerNorm over the 1152-wide QKV rows, in place in g_qkv.
// ---------------------------------------------------------------------------
__global__ void __launch_bounds__(256)
ln_kernel(const float* __restrict__ gamma, const float* __restrict__ beta)
{
    const int row = blockIdx.x;
    float* p = g_qkv + (size_t)row * QKV_O;
    const int tid = threadIdx.x;

    float s = 0.f, sq = 0.f;
    for (int i = tid; i < QKV_O; i += 256) {
        float v = p[i];
        s += v;
        sq += v * v;
    }
    __shared__ float red[256], red2[256];
    red[tid] = s; red2[tid] = sq;
    __syncthreads();
    for (int off = 128; off > 0; off >>= 1) {
        if (tid < off) {
            red[tid] += red[tid + off];
            red2[tid] += red2[tid + off];
        }
        __syncthreads();
    }
    const float inv_n = 1.0f / (float)QKV_O;
    float mean = red[0] * inv_n;
    float var = red2[0] * inv_n - mean * mean;
    float rstd = rsqrtf(var + 1e-5f);

    for (int i = tid; i < QKV_O; i += 256) {
        p[i] = (p[i] - mean) * rstd * gamma[i] + beta[i];
    }
}

// ---------------------------------------------------------------------------
// Causal MQA flash attention, tf32 mma.sync, register-resident softmax.
// Block: 128 queries x 1 head. 8 warps, warp owns 16 query rows (one m16 tile).
// KV tile = 64. Per-row softmax state lives in the owning quad's registers.
// Smem: Ks[64][68] (j,d), Vs[64][72] (j,d), Ps[128][68] (Q staging, then P).
// ---------------------------------------------------------------------------
#define KS_STRIDE 68
#define VS_STRIDE 72
#define PS_STRIDE 68
#define SM_VS (64 * KS_STRIDE)
#define SM_PS (SM_VS + 64 * VS_STRIDE)
#define ATT_SMEM_WORDS (SM_PS + 128 * PS_STRIDE)
#define ATT_SMEM_BYTES (ATT_SMEM_WORDS * 4)

__global__ void __launch_bounds__(256, 2)
attn_tc()
{
    extern __shared__ unsigned smu[];
    unsigned* Ks = smu;
    unsigned* Vs = smu + SM_VS;
    unsigned* Ps = smu + SM_PS;

    const int tid = threadIdx.x, lane = tid & 31, warp = tid >> 5;
    const int r = lane >> 2, c = lane & 3;
    const int b = blockIdx.z, h = blockIdx.y;
    const int qt = 15 - blockIdx.x;          // heavy tiles first
    const int q0 = qt * 128;
    const float* base = g_qkv + (size_t)b * SEQ * QKV_O;
    const int qoff = 2 * HD + h * HD;
    const int m0 = warp * 16;

    // Stage Q (tf32) into Ps region
#pragma unroll
    for (int i = 0; i < 8; i++) {
        int idx = tid + i * 256;            // 2048 float4 slots
        int row = idx >> 4;
        int c4 = (idx & 15) << 2;
        float4 v = *(const float4*)(base + (size_t)(q0 + row) * QKV_O + qoff + c4);
        unsigned* p = &Ps[row * PS_STRIDE + c4];
        p[0] = f2t(v.x); p[1] = f2t(v.y); p[2] = f2t(v.z); p[3] = f2t(v.w);
    }
    __syncthreads();

    // Preload Q fragments (rows m0+r, m0+r+8; k = 8*kk + c, +4)
    unsigned qf[8][4];
#pragma unroll
    for (int kk = 0; kk < 8; kk++) {
        const unsigned* p = &Ps[(m0 + r) * PS_STRIDE + kk * 8 + c];
        qf[kk][0] = p[0];
        qf[kk][1] = p[8 * PS_STRIDE];
        qf[kk][2] = p[4];
        qf[kk][3] = p[8 * PS_STRIDE + 4];
    }

    float o[8][4];
#pragma unroll
    for (int n = 0; n < 8; n++)
#pragma unroll
        for (int e = 0; e < 4; e++) o[n][e] = 0.f;
    float m_lo = -1e30f, m_hi = -1e30f, l_lo = 0.f, l_hi = 0.f;
    const int i_lo = q0 + m0 + r, i_hi = i_lo + 8;
    const float scale = 0.125f;              // 1/sqrt(64)

    const int ktmax = 2 * qt + 1;
    for (int kt = 0; kt <= ktmax; kt++) {
        const int k0 = kt * 64;
        __syncthreads();                     // Ks/Vs free (prev readers done; Q frags read)

        // Stage K,V tiles (tf32)
#pragma unroll
        for (int i = 0; i < 4; i++) {
            int idx = tid + i * 256;         // 1024 slots
            int j = idx >> 4;
            int c4 = (idx & 15) << 2;
            const float* src = base + (size_t)(k0 + j) * QKV_O;
            float4 kv = *(const float4*)(src + c4);
            float4 vv = *(const float4*)(src + HD + c4);
            unsigned* kp = &Ks[j * KS_STRIDE + c4];
            kp[0] = f2t(kv.x); kp[1] = f2t(kv.y); kp[2] = f2t(kv.z); kp[3] = f2t(kv.w);
            unsigned* vp = &Vs[j * VS_STRIDE + c4];
            vp[0] = f2t(vv.x); vp[1] = f2t(vv.y); vp[2] = f2t(vv.z); vp[3] = f2t(vv.w);
        }
        __syncthreads();

        // S = Q K^T : per warp 16x64, 8 n-tiles x 8 k-steps
        float s[8][4];
#pragma unroll
        for (int n = 0; n < 8; n++)
#pragma unroll
            for (int e = 0; e < 4; e++) s[n][e] = 0.f;
#pragma unroll
        for (int n = 0; n < 8; n++) {
#pragma unroll
            for (int kk = 0; kk < 8; kk++) {
                const unsigned* p = &Ks[(n * 8 + r) * KS_STRIDE + kk * 8 + c];
                unsigned bf[2] = {p[0], p[4]};
                mma8(s[n], qf[kk], bf);
            }
        }

        // Scale + causal mask
        const bool diag = (kt >= 2 * qt);
#pragma unroll
        for (int n = 0; n < 8; n++) {
            int j0 = k0 + n * 8 + 2 * c;
            if (diag) {
                s[n][0] = (j0     > i_lo) ? -1e30f : s[n][0] * scale;
                s[n][1] = (j0 + 1 > i_lo) ? -1e30f : s[n][1] * scale;
                s[n][2] = (j0     > i_hi) ? -1e30f : s[n][2] * scale;
                s[n][3] = (j0 + 1 > i_hi) ? -1e30f : s[n][3] * scale;
            } else {
                s[n][0] *= scale; s[n][1] *= scale;
                s[n][2] *= scale; s[n][3] *= scale;
            }
        }

        // Online softmax (row state in quad registers)
        float mx_lo = -1e30f, mx_hi = -1e30f;
#pragma unroll
        for (int n = 0; n < 8; n++) {
            mx_lo = fmaxf(mx_lo, fmaxf(s[n][0], s[n][1]));
            mx_hi = fmaxf(mx_hi, fmaxf(s[n][2], s[n][3]));
        }
        mx_lo = fmaxf(mx_lo, __shfl_xor_sync(0xffffffffu, mx_lo, 1));
        mx_lo = fmaxf(mx_lo, __shfl_xor_sync(0xffffffffu, mx_lo, 2));
        mx_hi = fmaxf(mx_hi, __shfl_xor_sync(0xffffffffu, mx_hi, 1));
        mx_hi = fmaxf(mx_hi, __shfl_xor_sync(0xffffffffu, mx_hi, 2));

        float mn_lo = fmaxf(m_lo, mx_lo), mn_hi = fmaxf(m_hi, mx_hi);
        float al_lo = __expf(m_lo - mn_lo), al_hi = __expf(m_hi - mn_hi);
        m_lo = mn_lo; m_hi = mn_hi;

        float sum_lo = 0.f, sum_hi = 0.f;
#pragma unroll
        for (int n = 0; n < 8; n++) {
            s[n][0] = __expf(s[n][0] - mn_lo);
            s[n][1] = __expf(s[n][1] - mn_lo);
            s[n][2] = __expf(s[n][2] - mn_hi);
            s[n][3] = __expf(s[n][3] - mn_hi);
            sum_lo += s[n][0] + s[n][1];
            sum_hi += s[n][2] + s[n][3];
        }
        sum_lo += __shfl_xor_sync(0xffffffffu, sum_lo, 1);
        sum_lo += __shfl_xor_sync(0xffffffffu, sum_lo, 2);
        sum_hi += __shfl_xor_sync(0xffffffffu, sum_hi, 1);
        sum_hi += __shfl_xor_sync(0xffffffffu, sum_hi, 2);
        l_lo = l_lo * al_lo + sum_lo;
        l_hi = l_hi * al_hi + sum_hi;

#pragma unroll
        for (int n = 0; n < 8; n++) {
            o[n][0] *= al_lo; o[n][1] *= al_lo;
            o[n][2] *= al_hi; o[n][3] *= al_hi;
        }

        // Store P (tf32) into warp-private Ps rows; warp-local ordering only
#pragma unroll
        for (int n = 0; n < 8; n++) {
            *(uint2*)&Ps[(m0 + r) * PS_STRIDE + n * 8 + 2 * c] =
                make_uint2(f2t(s[n][0]), f2t(s[n][1]));
            *(uint2*)&Ps[(m0 + r + 8) * PS_STRIDE + n * 8 + 2 * c] =
                make_uint2(f2t(s[n][2]), f2t(s[n][3]));
        }
        __syncwarp();

        // O += P V : 8 k-steps (j) x 8 n-tiles (d)
#pragma unroll
        for (int kk = 0; kk < 8; kk++) {
            const unsigned* p = &Ps[(m0 + r) * PS_STRIDE + kk * 8 + c];
            unsigned af[4];
            af[0] = p[0];
            af[1] = p[8 * PS_STRIDE];
            af[2] = p[4];
            af[3] = p[8 * PS_STRIDE + 4];
#pragma unroll
            for (int n = 0; n < 8; n++) {
                const unsigned* vp = &Vs[(kk * 8 + c) * VS_STRIDE + n * 8 + r];
                unsigned bf[2] = {vp[0], vp[4 * VS_STRIDE]};
                mma8(o[n], af, bf);
            }
        }
    }

    // Epilogue: O / l
    float inv_lo = 1.f / l_lo, inv_hi = 1.f / l_hi;
    float* out_lo = g_attn + (size_t)(b * SEQ + i_lo) * HID + h * HD;
    float* out_hi = g_attn + (size_t)(b * SEQ + i_hi) * HID + h * HD;
#pragma unroll
    for (int n = 0; n < 8; n++) {
        int col = n * 8 + 2 * c;
        *(float2*)(out_lo + col) = make_float2(o[n][0] * inv_lo, o[n][1] * inv_lo);
        *(float2*)(out_hi + col) = make_float2(o[n][2] * inv_hi, o[n][3] * inv_hi);
    }
}

// ---------------------------------------------------------------------------
extern "C" void kernel_launch(void* const* d_in, const int* in_sizes, int n_in,
                              void* d_out, int out_size)
{
    const float* x     = (const float*)d_in[0];   // (2, 2048, 1024)
    const float* Wqkv  = (const float*)d_in[1];   // (1152, 1024)
    const float* gamma = (const float*)d_in[2];   // (1152,)
    const float* beta  = (const float*)d_in[3];   // (1152,)
    const float* Wfc   = (const float*)d_in[4];   // (1024, 1024)
    float* out = (float*)d_out;                   // (2, 2048, 1024)

    void* qkv_p = nullptr;
    void* attn_p = nullptr;
    cudaGetSymbolAddress(&qkv_p, g_qkv);
    cudaGetSymbolAddress(&attn_p, g_attn);
    float* qkv = (float*)qkv_p;
    float* attn = (float*)attn_p;

    cudaFuncSetAttribute(attn_tc, cudaFuncAttributeMaxDynamicSharedMemorySize,
                         ATT_SMEM_BYTES);

    dim3 blk(256);

    // 1) QKV GEMM: g_qkv[4096,1152] = x[4096,1024] @ Wqkv[1152,1024]^T (tf32 TC)
    gemm_nt_tc<<<dim3(QKV_O / 128, ROWS / 128), blk>>>(x, Wqkv, qkv, ROWS, QKV_O, HID);

    // 2) LayerNorm in place (fp32)
    ln_kernel<<<ROWS, blk>>>(gamma, beta);

    // 3) Causal MQA attention -> g_attn (tf32 TC, register softmax)
    attn_tc<<<dim3(SEQ / 128, NH, BATCH), blk, ATT_SMEM_BYTES>>>();

    // 4) Output projection: out = g_attn @ Wfc^T (tf32 TC)
    gemm_nt_tc<<<dim3(HID / 128, ROWS / 128), blk>>>(attn, Wfc, out, ROWS, HID, HID);
}